// round 17
// baseline (speedup 1.0000x reference)
#include <cuda_runtime.h>
#include <cuda_fp16.h>
#include <cstdint>

#define BATCH     512
#define SIZE_IN   1024
#define SIZE_OUT  256
#define NQ        16

#define BT        32                 // batch tile per CTA
#define ISPLIT    37                 // 16 * 37 = 592 = 148 SMs * 4 CTAs exactly
#define NPHMAX    14                 // ceil(28/2)
#define NTHREADS  512
#define SLOT_B    16384              // bytes per slot: 2 features x 16 rows x 512 B fp16
#define RING_B    (2 * SLOT_B)       // 32 KB dynamic smem (double buffer)

// fp16 copy of the weight table (8 MB static scratch; no allocation allowed)
__device__ __half g_tableh[NQ * SIZE_IN * SIZE_OUT];

// Fused prep: table fp32 -> fp16, 4 elems/thread (1 LDG.128 + 1 STG.64),
// 1M threads for MLP; first 512 blocks also write out[b,:] = bias.
__global__ void il_prep(const float* __restrict__ table,
                        const float* __restrict__ bias,
                        float* __restrict__ out) {
    const size_t i = ((size_t)blockIdx.x * 256 + threadIdx.x) * 4;
    const float4 a = *reinterpret_cast<const float4*>(table + i);
    __half2 h[2];
    h[0] = __floats2half2_rn(a.x, a.y);
    h[1] = __floats2half2_rn(a.z, a.w);
    *reinterpret_cast<uint2*>(g_tableh + i) = *reinterpret_cast<uint2*>(h);

    if (blockIdx.x < BATCH) {   // out[b, o] = bias[o]
        out[blockIdx.x * SIZE_OUT + threadIdx.x] = bias[threadIdx.x];
    }
}

__device__ __forceinline__ void cp_async16(uint32_t saddr, const void* gptr) {
    asm volatile("cp.async.cg.shared.global [%0], [%1], 16;\n" :: "r"(saddr), "l"(gptr));
}
__device__ __forceinline__ void cp_commit() {
    asm volatile("cp.async.commit_group;\n" ::: "memory");
}
__device__ __forceinline__ void red_v4(float* p, float a, float b, float c, float d) {
    asm volatile("red.global.add.v4.f32 [%0], {%1, %2, %3, %4};"
                 :: "l"(p), "f"(a), "f"(b), "f"(c), "f"(d) : "memory");
}

// acc (packed f32x2) += float2(s) ; 2 F2F (H0/H1 selectors) + 1 packed add
__device__ __forceinline__ void acc_h2(unsigned long long& acc, __half2 s) {
    const uint32_t sb = *reinterpret_cast<uint32_t*>(&s);
    unsigned long long f2;
    asm("{\n\t.reg .b16 lo, hi;\n\t.reg .f32 flo, fhi;\n\t"
        "mov.b32 {lo, hi}, %1;\n\t"
        "cvt.f32.f16 flo, lo;\n\t"
        "cvt.f32.f16 fhi, hi;\n\t"
        "mov.b64 %0, {flo, fhi};\n\t}"
        : "=l"(f2) : "r"(sb));
    asm("add.rn.f32x2 %0, %0, %1;" : "+l"(acc) : "l"(f2));
}

// One CTA: 32 batches x (27..28) features x 256 outputs, fp16 weights,
// 512 threads @ <=32 regs -> 4 CTAs/SM = 64 warps/SM.
// Inner math: HFMA2 over the 2 features of a phase + packed f32x2 accumulate.
__global__ __launch_bounds__(NTHREADS, 4)
void il_main(const float* __restrict__ x,
             const int* __restrict__ indices,   // JAX canonicalizes int64 -> int32
             float* __restrict__ out) {
    extern __shared__ __align__(16) __half sW[];   // 2 x 8192 halves (32 KB)
    __shared__ float4 sxq[BT][NPHMAX];   // {bits(half2 x0), bits(half2 x1), bits(off0), bits(off1)}

    const int b0  = blockIdx.x * BT;
    const int lo  = (int)(((long long)blockIdx.y * SIZE_IN) / ISPLIT);
    const int hi  = (int)(((long long)(blockIdx.y + 1) * SIZE_IN) / ISPLIT);
    const int len = hi - lo;             // 27 or 28
    const int nph = (len + 1) >> 1;      // 14
    const int t   = threadIdx.x;
    const int og  = t & 31;              // output columns og*8 .. og*8+7
    const int bg  = t >> 5;              // batches bg*2, bg*2+1 (warp-uniform)

    const uint32_t sW_u32 = (uint32_t)__cvta_generic_to_shared(sW);

    // Staging map: 16 KB/phase = 1024 x 16B segs; thread covers segs t, t+512.
    const uint32_t off0s = (uint32_t)(((t >> 5) & 15) * 512 + (t & 31) * 16);   // feature 0
    const uint32_t off1s = 8192u + off0s;                                        // feature 1
    const __half* sb0 = g_tableh + ((size_t)((t >> 5) & 15) * SIZE_IN) * SIZE_OUT + (t & 31) * 8;

    // Prefetch phase 0 into buffer 0 (one commit group).
    {
        cp_async16(sW_u32 + off0s, sb0 + (size_t)lo * SIZE_OUT);
        if (lo + 1 < hi) cp_async16(sW_u32 + off1s, sb0 + (size_t)(lo + 1) * SIZE_OUT);
        cp_commit();
    }

    // Preload sxq: thread covers batch bl = t>>4, phase p = t&15.
    {
        const int bl = t >> 4;
        const int p  = t & 15;
        if (p < nph) {
            const float* xp = x       + (size_t)(b0 + bl) * SIZE_IN;
            const int*   qp = indices + (size_t)(b0 + bl) * SIZE_IN;
            const int i0 = lo + 2 * p;
            float4 v;
            const __half2 hx0 = __floats2half2_rn(xp[i0], xp[i0]);
            v.x = __int_as_float((int)*reinterpret_cast<const uint32_t*>(&hx0));
            v.z = __int_as_float(qp[i0] * SIZE_OUT);        // offset in halves, feature-0 region
            if (i0 + 1 < hi) {
                const __half2 hx1 = __floats2half2_rn(xp[i0 + 1], xp[i0 + 1]);
                v.y = __int_as_float((int)*reinterpret_cast<const uint32_t*>(&hx1));
                v.w = __int_as_float(4096 + qp[i0 + 1] * SIZE_OUT);
            } else {
                v.y = __int_as_float(0);        // half2{0,0}: contributes exactly 0
                v.w = __int_as_float(4096);     // safe, finite region
            }
            sxq[bl][p] = v;
        }
    }

    // Packed accumulators: acc2[bl][q] = {out og*8+2q, og*8+2q+1} as f32x2
    unsigned long long acc2[2][4];
    #pragma unroll
    for (int bl = 0; bl < 2; bl++)
        #pragma unroll
        for (int q = 0; q < 4; q++) acc2[bl][q] = 0ull;

    for (int p = 0; p < nph; p++) {
        const int buf = p & 1;

        asm volatile("cp.async.wait_group 0;" ::: "memory");
        __syncthreads();   // staged data visible; all readers done with buf^1

        // Prefetch phase p+1 into the other buffer.
        if (p + 1 < nph) {
            const int i0 = lo + 2 * (p + 1);
            const uint32_t dst = sW_u32 + (uint32_t)((buf ^ 1) * SLOT_B);
            cp_async16(dst + off0s, sb0 + (size_t)i0 * SIZE_OUT);
            if (i0 + 1 < hi) cp_async16(dst + off1s, sb0 + (size_t)(i0 + 1) * SIZE_OUT);
            cp_commit();
        }

        const __half* wb = sW + buf * 8192;

        #pragma unroll
        for (int bl = 0; bl < 2; bl++) {
            const float4 v = sxq[bg * 2 + bl][p];   // 16B broadcast
            const uint32_t xb0 = __float_as_uint(v.x);
            const uint32_t xb1 = __float_as_uint(v.y);
            const __half2 xh0 = *reinterpret_cast<const __half2*>(&xb0);
            const __half2 xh1 = *reinterpret_cast<const __half2*>(&xb1);
            const uint4 u0 = *reinterpret_cast<const uint4*>(
                wb + __float_as_int(v.z) + og * 8);
            const uint4 u1 = *reinterpret_cast<const uint4*>(
                wb + __float_as_int(v.w) + og * 8);
            const __half2* h0 = reinterpret_cast<const __half2*>(&u0);
            const __half2* h1 = reinterpret_cast<const __half2*>(&u1);
            #pragma unroll
            for (int q = 0; q < 4; q++) {
                __half2 s = __hmul2(h0[q], xh0);
                s = __hfma2(h1[q], xh1, s);
                acc_h2(acc2[bl][q], s);
            }
        }
    }

    // Combine split-k partials: unpack f32x2 accumulators, 2 red.v4 per batch.
    #pragma unroll
    for (int bl = 0; bl < 2; bl++) {
        float a[8];
        #pragma unroll
        for (int q = 0; q < 4; q++) {
            asm("mov.b64 {%0, %1}, %2;"
                : "=f"(a[q * 2]), "=f"(a[q * 2 + 1]) : "l"(acc2[bl][q]));
        }
        const int b = b0 + bg * 2 + bl;
        float* op = out + (size_t)b * SIZE_OUT + og * 8;
        red_v4(op,     a[0], a[1], a[2], a[3]);
        red_v4(op + 4, a[4], a[5], a[6], a[7]);
    }
}

extern "C" void kernel_launch(void* const* d_in, const int* in_sizes, int n_in,
                              void* d_out, int out_size) {
    const float* x       = (const float*)d_in[0];
    const int*   indices = (const int*)d_in[1];
    const float* table   = (const float*)d_in[2];
    const float* bias    = (const float*)d_in[3];
    float*       out     = (float*)d_out;

    static int attr_set = 0;
    if (!attr_set) {
        cudaFuncSetAttribute(il_main, cudaFuncAttributeMaxDynamicSharedMemorySize, RING_B);
        attr_set = 1;
    }

    // prep: 4,194,304 elems / 4 per thread / 256 per block = 4096 blocks
    il_prep<<<4096, 256>>>(table, bias, out);

    dim3 grid(BATCH / BT, ISPLIT);   // 16 x 37 = 592 CTAs = 148 SMs * 4
    il_main<<<grid, NTHREADS, RING_B>>>(x, indices, out);
}